// round 15
// baseline (speedup 1.0000x reference)
#include <cuda_runtime.h>
#include <cuda_fp16.h>
#include <cstdint>

#define T_TOK   2048
#define HID     2048
#define NEXP    64
#define INTER   512
#define SINTER  1024
#define TOPK    8
#define ROWS_SHARED 4096
#define ROWS_MOE    (T_TOK*TOPK)
#define ROWS_TOTAL  (ROWS_SHARED + ROWS_MOE)

#define SA   72   // A smem row stride (halves): K=64 + pad 8
#define SB1  72   // stage1 B row stride (halves)
#define SB2  136  // stage2 B row stride (halves)

#define S1_ASTG (128*SA*2)
#define S1_BSTG (64*SB1*2)
#define S2_ASTG (128*SA*2)
#define S2_BSTG (64*SB2*2)

// segment sizes in float4 units
#define NX4   ((long)T_TOK*HID/4)
#define NWG4  ((long)NEXP*HID*INTER/4)
#define NSG4  ((long)HID*SINTER/4)
#define NWD4  ((long)NEXP*INTER*HID/4)
#define NSD4  ((long)SINTER*HID/4)
#define NOUT4 ((long)T_TOK*HID/4)

// ---------------- device scratch ----------------
__device__ float    g_logits[T_TOK*NEXP];
__device__ int      g_sel  [T_TOK*TOPK];
__device__ float    g_selw [T_TOK*TOPK];
__device__ int      g_cnt  [NEXP];
__device__ int      g_off  [NEXP];
__device__ int      g_cur  [NEXP];
__device__ int      g_tok  [ROWS_MOE];
__device__ float    g_tw   [ROWS_MOE];
__device__ __half   g_Hh[(size_t)ROWS_TOTAL*INTER];
__device__ __half   g_x16[(size_t)T_TOK*HID];
__device__ __half   g_wg16[(size_t)NEXP*HID*INTER];
__device__ __half   g_wu16[(size_t)NEXP*HID*INTER];
__device__ __half   g_wd16[(size_t)NEXP*INTER*HID];
__device__ __half   g_sg16[(size_t)HID*SINTER];
__device__ __half   g_su16[(size_t)HID*SINTER];
__device__ __half   g_sd16[(size_t)SINTER*HID];

// ---------------- helpers ----------------
__device__ __forceinline__ uint32_t smem_u32(const void* p) {
    uint32_t a;
    asm("{ .reg .u64 t; cvta.to.shared.u64 t, %1; cvt.u32.u64 %0, t; }" : "=r"(a) : "l"(p));
    return a;
}
__device__ __forceinline__ uint32_t packh2(float x, float y) {
    __half2 h = __floats2half2_rn(x, y);
    return *(uint32_t*)&h;
}
__device__ __forceinline__ void mma16(float c[4], const uint32_t a[4],
                                      uint32_t b0, uint32_t b1) {
    asm volatile(
        "mma.sync.aligned.m16n8k16.row.col.f32.f16.f16.f32 "
        "{%0,%1,%2,%3}, {%4,%5,%6,%7}, {%8,%9}, {%0,%1,%2,%3};\n"
        : "+f"(c[0]), "+f"(c[1]), "+f"(c[2]), "+f"(c[3])
        : "r"(a[0]), "r"(a[1]), "r"(a[2]), "r"(a[3]), "r"(b0), "r"(b1));
}
__device__ __forceinline__ void ldsm_x4(uint32_t r[4], uint32_t addr) {
    asm volatile("ldmatrix.sync.aligned.m8n8.x4.shared.b16 {%0,%1,%2,%3}, [%4];"
        : "=r"(r[0]), "=r"(r[1]), "=r"(r[2]), "=r"(r[3]) : "r"(addr));
}
__device__ __forceinline__ void ldsm_x4t(uint32_t r[4], uint32_t addr) {
    asm volatile("ldmatrix.sync.aligned.m8n8.x4.trans.shared.b16 {%0,%1,%2,%3}, [%4];"
        : "=r"(r[0]), "=r"(r[1]), "=r"(r[2]), "=r"(r[3]) : "r"(addr));
}
__device__ __forceinline__ void red_add_v2(float* p, float a, float b) {
    asm volatile("red.global.add.v2.f32 [%0], {%1, %2};"
        :: "l"(p), "f"(a), "f"(b) : "memory");
}
__device__ __forceinline__ void cp16(uint32_t dst, const void* src) {
    asm volatile("cp.async.cg.shared.global [%0], [%1], 16;"
        :: "r"(dst), "l"(src) : "memory");
}
#define CP_COMMIT() asm volatile("cp.async.commit_group;" ::: "memory")
#define CP_WAIT1()  asm volatile("cp.async.wait_group 1;"  ::: "memory")

__device__ __forceinline__ uint2 cvt4(const float4 v) {
    return make_uint2(packh2(v.x, v.y), packh2(v.z, v.w));
}

// ---------------- 0) all conversions + zero out ----------------
__global__ void cvt_all(const float4* __restrict__ x,
                        const float4* __restrict__ wg,
                        const float4* __restrict__ wu,
                        const float4* __restrict__ wd,
                        const float4* __restrict__ sg,
                        const float4* __restrict__ su,
                        const float4* __restrict__ sd,
                        float4* __restrict__ out) {
    const long i0 = (long)blockIdx.x*blockDim.x + threadIdx.x;
    const long st = (long)gridDim.x*blockDim.x;
    uint2* xd  = (uint2*)g_x16;
    uint2* wgd = (uint2*)g_wg16;
    uint2* wud = (uint2*)g_wu16;
    uint2* wdd = (uint2*)g_wd16;
    uint2* sgd = (uint2*)g_sg16;
    uint2* sud = (uint2*)g_su16;
    uint2* sdd = (uint2*)g_sd16;
    for (long i = i0; i < NX4;  i += st) xd[i]  = cvt4(x[i]);
    for (long i = i0; i < NWG4; i += st) wgd[i] = cvt4(wg[i]);
    for (long i = i0; i < NWG4; i += st) wud[i] = cvt4(wu[i]);
    for (long i = i0; i < NWD4; i += st) wdd[i] = cvt4(wd[i]);
    for (long i = i0; i < NSG4; i += st) sgd[i] = cvt4(sg[i]);
    for (long i = i0; i < NSG4; i += st) sud[i] = cvt4(su[i]);
    for (long i = i0; i < NSD4; i += st) sdd[i] = cvt4(sd[i]);
    for (long i = i0; i < NOUT4; i += st) out[i] = make_float4(0.f,0.f,0.f,0.f);
}

// ---------------- 1) router GEMM + cnt zero ----------------
__global__ void router_gemm(const float* __restrict__ x, const float* __restrict__ rw) {
    if (blockIdx.x == 0 && threadIdx.x < NEXP) g_cnt[threadIdx.x] = 0;
    __shared__ float As[32][33];
    __shared__ float Bs[32][65];
    const int tid = threadIdx.x;
    const int t0  = blockIdx.x * 32;
    const int m   = tid >> 3, nb = tid & 7;
    float acc[8] = {};
    for (int kt = 0; kt < HID; kt += 32) {
        __syncthreads();
        {   int r = tid >> 3, c = (tid & 7) * 4;
            const float4 v = *(const float4*)(x + (size_t)(t0 + r)*HID + kt + c);
            As[r][c] = v.x; As[r][c+1] = v.y; As[r][c+2] = v.z; As[r][c+3] = v.w; }
        #pragma unroll
        for (int i = 0; i < 8; i++) {
            int idx = tid + i*256; int e = idx >> 5, k = idx & 31;
            Bs[k][e] = rw[(size_t)e*HID + kt + k];
        }
        __syncthreads();
        #pragma unroll
        for (int k = 0; k < 32; k++) {
            float a = As[m][k];
            #pragma unroll
            for (int j = 0; j < 8; j++) acc[j] += a * Bs[k][nb + 8*j];
        }
    }
    #pragma unroll
    for (int j = 0; j < 8; j++) g_logits[(size_t)(t0+m)*NEXP + nb + 8*j] = acc[j];
}

// ---------------- 2) top-k ----------------
__global__ void topk_kernel() {
    int t = blockIdx.x * blockDim.x + threadIdx.x;
    if (t >= T_TOK) return;
    float l[NEXP];
    #pragma unroll
    for (int e = 0; e < NEXP; e++) l[e] = g_logits[(size_t)t*NEXP + e];
    float bw[TOPK]; int bi[TOPK];
    for (int i = 0; i < TOPK; i++) {
        float mv = -1e30f; int mi = 0;
        for (int e = 0; e < NEXP; e++) if (l[e] > mv) { mv = l[e]; mi = e; }
        bw[i] = mv; bi[i] = mi; l[mi] = -1e30f;
    }
    float s = 0.f, mx = bw[0], w[TOPK];
    #pragma unroll
    for (int i = 0; i < TOPK; i++) { w[i] = expf(bw[i] - mx); s += w[i]; }
    float inv = 1.f / s;
    #pragma unroll
    for (int i = 0; i < TOPK; i++) {
        g_sel [t*TOPK+i] = bi[i];
        g_selw[t*TOPK+i] = w[i]*inv;
        atomicAdd(&g_cnt[bi[i]], 1);
    }
}

// ---------------- 3) prefix scan + scatter ----------------
__global__ void scan_kernel() {
    const int i = threadIdx.x;
    __shared__ int tmp[NEXP];
    int v = g_cnt[i];
    tmp[i] = v;
    __syncthreads();
    #pragma unroll
    for (int d = 1; d < NEXP; d <<= 1) {
        int o = (i >= d) ? tmp[i-d] : 0;
        __syncthreads();
        tmp[i] += o;
        __syncthreads();
    }
    int excl = tmp[i] - v;
    g_off[i] = excl; g_cur[i] = excl;
}
__global__ void scatter_kernel() {
    int idx = blockIdx.x*blockDim.x + threadIdx.x;
    if (idx >= T_TOK*TOPK) return;
    int t = idx >> 3;
    int e = g_sel[idx];
    int pos = atomicAdd(&g_cur[e], 1);
    g_tok[pos] = t; g_tw[pos] = g_selw[idx];
}

// ---------------- 4) stage 1: 3-stage K64, fragment double-buffer ----------
// grid (16, 66, 8); CTA M=128, N=64g+64u, 128 threads
#define S1_A    1024
#define S1_BG   (S1_A  + 3*S1_ASTG)
#define S1_BU   (S1_BG + 3*S1_BSTG)
#define S1_SMEM (S1_BU + 3*S1_BSTG)
__global__ void __launch_bounds__(128, 2)
stage1_kernel() {
    const int s = blockIdx.y;
    int nrows, hbase, ldb, offmoe = 0;
    const __half *Bg, *Bu;
    if (s < 2) {
        nrows = T_TOK; hbase = s*T_TOK; ldb = SINTER;
        Bg = g_sg16 + s*INTER; Bu = g_su16 + s*INTER;
    } else {
        int e = s - 2;
        nrows = g_cnt[e]; offmoe = g_off[e]; hbase = ROWS_SHARED + offmoe; ldb = INTER;
        Bg = g_wg16 + (size_t)e*HID*INTER; Bu = g_wu16 + (size_t)e*HID*INTER;
    }
    const int m0 = blockIdx.x * 128;
    if (m0 >= nrows) return;
    const int n0   = blockIdx.z * 64;
    const int nloc = nrows - m0;

    extern __shared__ char smraw[];
    int*    s_tok = (int*)smraw;
    float*  s_w   = (float*)(smraw + 512);
    const uint32_t aB  = smem_u32(smraw + S1_A);
    const uint32_t bgB = smem_u32(smraw + S1_BG);
    const uint32_t buB = smem_u32(smraw + S1_BU);

    const int tid = threadIdx.x;
    {
        int r = m0 + tid;
        if (r < nrows) {
            if (s < 2) { s_tok[tid] = r; s_w[tid] = 1.f; }
            else       { s_tok[tid] = g_tok[offmoe + r]; s_w[tid] = g_tw[offmoe + r]; }
        } else { s_tok[tid] = (s < 2) ? 0 : g_tok[offmoe]; s_w[tid] = 0.f; }
    }
    __syncthreads();

    const int lane = tid & 31, warp = tid >> 5;
    const int wm = warp >> 1, wn = warp & 1;
    const int l4 = lane >> 2, lq = lane & 3;
    const int lr = lane & 15, lc = lane >> 4;
    float cg[4][4][4] = {}, cu[4][4][4] = {};

    const uint32_t aFrag = aB  + (uint32_t)(wm*64 + lr)*(SA*2) + lc*16;
    const uint32_t gFrag = bgB + (uint32_t)lr*(SB1*2) + wn*64 + lc*16;
    const uint32_t uFrag = buB + (uint32_t)lr*(SB1*2) + wn*64 + lc*16;

    const int arow = tid >> 3, acol = (tid & 7)*8;
    const __half* srcA[8];
    uint32_t dA[8];
    #pragma unroll
    for (int i = 0; i < 8; i++) {
        srcA[i] = g_x16 + (size_t)s_tok[arow + 16*i]*HID + acol;
        dA[i]   = aB + (uint32_t)((arow + 16*i)*SA + acol)*2;
    }
    const __half* srcG[4]; const __half* srcU[4];
    uint32_t dG[4], dU[4];
    #pragma unroll
    for (int i = 0; i < 4; i++) {
        int br = arow + 16*i;
        srcG[i] = Bg + (size_t)br*ldb + n0 + acol;
        srcU[i] = Bu + (size_t)br*ldb + n0 + acol;
        dG[i] = bgB + (uint32_t)(br*SB1 + acol)*2;
        dU[i] = buB + (uint32_t)(br*SB1 + acol)*2;
    }

    const int NT = HID / 64;
    auto issue = [&](int tile) {
        int st = tile % 3, kt = tile * 64;
        #pragma unroll
        for (int i = 0; i < 8; i++) cp16(dA[i] + st*S1_ASTG, srcA[i] + kt);
        #pragma unroll
        for (int i = 0; i < 4; i++) {
            cp16(dG[i] + st*S1_BSTG, srcG[i] + (size_t)kt*ldb);
            cp16(dU[i] + st*S1_BSTG, srcU[i] + (size_t)kt*ldb);
        }
    };

    uint32_t fa[2][4][4], fg[2][2][4], fu[2][2][4];
    auto ldfrag = [&](int st, int ks, int buf) {
        const uint32_t aOff = aFrag + (uint32_t)st*S1_ASTG + ks*32;
        const uint32_t gOff = gFrag + (uint32_t)st*S1_BSTG + ks*16*(SB1*2);
        const uint32_t uOff = uFrag + (uint32_t)st*S1_BSTG + ks*16*(SB1*2);
        #pragma unroll
        for (int mi = 0; mi < 4; mi++)
            ldsm_x4(fa[buf][mi], aOff + mi*16*(SA*2));
        #pragma unroll
        for (int ni = 0; ni < 2; ni++) {
            ldsm_x4t(fg[buf][ni], gOff + ni*32);
            ldsm_x4t(fu[buf][ni], uOff + ni*32);
        }
    };
    auto mmablk = [&](int buf) {
        #pragma unroll
        for (int mi = 0; mi < 4; mi++)
            #pragma unroll
            for (int ni = 0; ni < 2; ni++) {
                mma16(cg[mi][2*ni],   fa[buf][mi], fg[buf][ni][0], fg[buf][ni][1]);
                mma16(cg[mi][2*ni+1], fa[buf][mi], fg[buf][ni][2], fg[buf][ni][3]);
                mma16(cu[mi][2*ni],   fa[buf][mi], fu[buf][ni][0], fu[buf][ni][1]);
                mma16(cu[mi][2*ni+1], fa[buf][mi], fu[buf][ni][2], fu[buf][ni][3]);
            }
    };

    issue(0); CP_COMMIT();
    issue(1); CP_COMMIT();
    #pragma unroll 1
    for (int it = 0; it < NT; it++) {
        CP_WAIT1();
        __syncthreads();
        if (it + 2 < NT) issue(it + 2);
        CP_COMMIT();
        const int st = it % 3;
        ldfrag(st, 0, 0);
        #pragma unroll
        for (int ks = 0; ks < 4; ks++) {
            if (ks < 3) ldfrag(st, ks + 1, (ks + 1) & 1);
            mmablk(ks & 1);
        }
    }

    #pragma unroll
    for (int mi = 0; mi < 4; mi++) {
        int r0 = wm*64 + mi*16 + l4;
        int r1 = r0 + 8;
        float w0 = (r0 < nloc) ? s_w[r0] : 0.f;
        float w1 = (r1 < nloc) ? s_w[r1] : 0.f;
        #pragma unroll
        for (int nj = 0; nj < 4; nj++) {
            int c = wn*32 + nj*8 + 2*lq;
            if (r0 < nloc) {
                float g0 = cg[mi][nj][0], u0 = cu[mi][nj][0];
                float g1 = cg[mi][nj][1], u1 = cu[mi][nj][1];
                float h0 = g0 / (1.f + __expf(-g0)) * u0 * w0;
                float h1 = g1 / (1.f + __expf(-g1)) * u1 * w0;
                *(uint32_t*)(g_Hh + (size_t)(hbase + m0 + r0)*INTER + n0 + c) = packh2(h0, h1);
            }
            if (r1 < nloc) {
                float g2 = cg[mi][nj][2], u2 = cu[mi][nj][2];
                float g3 = cg[mi][nj][3], u3 = cu[mi][nj][3];
                float h2 = g2 / (1.f + __expf(-g2)) * u2 * w1;
                float h3 = g3 / (1.f + __expf(-g3)) * u3 * w1;
                *(uint32_t*)(g_Hh + (size_t)(hbase + m0 + r1)*INTER + n0 + c) = packh2(h2, h3);
            }
        }
    }
}

// ---------------- 5) stage 2: 3-stage K64, fragment double-buffer ----------
// grid (16, 66, 16); CTA M=128, N=128, 128 threads
#define S2_A    512
#define S2_B    (S2_A + 3*S2_ASTG)
#define S2_SMEM (S2_B + 3*S2_BSTG)
__global__ void __launch_bounds__(128, 2)
stage2_kernel(float* __restrict__ out) {
    const int s = blockIdx.y;
    int nrows, hbase, offmoe = 0; const __half* Bd;
    if (s < 2) { nrows = T_TOK; hbase = s*T_TOK; Bd = g_sd16 + (size_t)s*INTER*HID; }
    else { int e = s-2; nrows = g_cnt[e]; offmoe = g_off[e]; hbase = ROWS_SHARED + offmoe;
           Bd = g_wd16 + (size_t)e*INTER*HID; }
    const int m0 = blockIdx.x * 128;
    if (m0 >= nrows) return;
    const int n0   = blockIdx.z * 128;
    const int nloc = nrows - m0;

    extern __shared__ char smraw[];
    int* s_tok = (int*)smraw;
    const uint32_t aB = smem_u32(smraw + S2_A);
    const uint32_t bB = smem_u32(smraw + S2_B);

    const int tid = threadIdx.x, lane = tid & 31, warp = tid >> 5;
    {
        int r = m0 + tid;
        if (r < nrows) s_tok[tid] = (s < 2) ? r : g_tok[offmoe + r];
        else           s_tok[tid] = 0;
    }
    __syncthreads();

    const int wm = warp >> 1, wn = warp & 1;
    const int l4 = lane >> 2, lq = lane & 3;
    const int lr = lane & 15, lc = lane >> 4;
    float cc[4][8][4] = {};

    const uint32_t aFrag = aB + (uint32_t)(wm*64 + lr)*(SA*2) + lc*16;
    const uint32_t bFrag = bB + (uint32_t)lr*(SB2*2) + wn*128 + lc*16;

    const int arow = tid >> 3, acol = (tid & 7)*8;
    const int brow = tid >> 4, bcol = (tid & 15)*8;
    const __half* srcA[8];
    uint32_t dA[8];
    #pragma unroll
    for (int i = 0; i < 8; i++) {
        int r = arow + 16*i;
        int rr = (r < nloc) ? r : 0;
        srcA[i] = g_Hh + (size_t)(hbase + m0 + rr)*INTER + acol;
        dA[i]   = aB + (uint32_t)(r*SA + acol)*2;
    }
    const __half* srcB[8];
    uint32_t dB[8];
    #pragma unroll
    for (int i = 0; i < 8; i++) {
        int r = brow + 8*i;
        srcB[i] = Bd + (size_t)r*HID + n0 + bcol;
        dB[i]   = bB + (uint32_t)(r*SB2 + bcol)*2;
    }

    const int NT = INTER / 64;
    auto issue = [&](int tile) {
        int st = tile % 3, kt = tile * 64;
        #pragma unroll
        for (int i = 0; i < 8; i++) cp16(dA[i] + st*S2_ASTG, srcA[i] + kt);
        #pragma unroll
        for (int i = 0; i < 8; i++) cp16(dB[i] + st*S2_BSTG, srcB[i] + (size_t)kt*HID);
    };

    uint32_t fa[2][4][4], fb[2][4][4];
    auto ldfrag = [&](int st, int ks, int buf) {
        const uint32_t aOff = aFrag + (uint32_t)st*S2_ASTG + ks*32;
        const uint32_t bOff = bFrag + (uint32_t)st*S2_BSTG + ks*16*(SB2*2);
        #pragma unroll
        for (int mi = 0; mi < 4; mi++)
            ldsm_x4(fa[buf][mi], aOff + mi*16*(SA*2));
        #pragma unroll
        for (int ni = 0; ni < 4; ni++)
            ldsm_x4t(fb[buf][ni], bOff + ni*32);
    };
    auto mmablk = [&](int buf) {
        #pragma unroll
        for (int mi = 0; mi < 4; mi++)
            #pragma unroll
            for (int ni = 0; ni < 4; ni++) {
                mma16(cc[mi][2*ni],   fa[buf][mi], fb[buf][ni][0], fb[buf][ni][1]);
                mma16(cc[mi][2*ni+1], fa[buf][mi], fb[buf][ni][2], fb[buf][ni][3]);
            }
    };

    issue(0); CP_COMMIT();
    issue(1); CP_COMMIT();
    #pragma unroll 1
    for (int it = 0; it < NT; it++) {
        CP_WAIT1();
        __syncthreads();
        if (it + 2 < NT) issue(it + 2);
        CP_COMMIT();
        const int st = it % 3;
        ldfrag(st, 0, 0);
        #pragma unroll
        for (int ks = 0; ks < 4; ks++) {
            if (ks < 3) ldfrag(st, ks + 1, (ks + 1) & 1);
            mmablk(ks & 1);
        }
    }

    #pragma unroll
    for (int mi = 0; mi < 4; mi++) {
        int r0 = wm*64 + mi*16 + l4;
        int r1 = r0 + 8;
        int tk0 = s_tok[r0], tk1 = s_tok[r1];
        #pragma unroll
        for (int nj = 0; nj < 8; nj++) {
            int c = n0 + wn*64 + nj*8 + 2*lq;
            if (r0 < nloc)
                red_add_v2(out + (size_t)tk0*HID + c, cc[mi][nj][0], cc[mi][nj][1]);
            if (r1 < nloc)
                red_add_v2(out + (size_t)tk1*HID + c, cc[mi][nj][2], cc[mi][nj][3]);
        }
    }
}

// ---------------- launch (serial stream, R13 structure) ----------------
extern "C" void kernel_launch(void* const* d_in, const int* in_sizes, int n_in,
                              void* d_out, int out_size) {
    const float* x  = (const float*)d_in[0];
    const float* rw = (const float*)d_in[1];
    const float* wg = (const float*)d_in[2];
    const float* wu = (const float*)d_in[3];
    const float* wd = (const float*)d_in[4];
    const float* sg = (const float*)d_in[5];
    const float* su = (const float*)d_in[6];
    const float* sd = (const float*)d_in[7];
    float* out = (float*)d_out;

    static bool attr_done = false;
    if (!attr_done) {
        cudaFuncSetAttribute(stage1_kernel, cudaFuncAttributeMaxDynamicSharedMemorySize, S1_SMEM);
        cudaFuncSetAttribute(stage2_kernel, cudaFuncAttributeMaxDynamicSharedMemorySize, S2_SMEM);
        attr_done = true;
    }

    router_gemm   <<<64, 256>>>(x, rw);
    cvt_all       <<<4096, 256>>>((const float4*)x,  (const float4*)wg,
                                  (const float4*)wu, (const float4*)wd,
                                  (const float4*)sg, (const float4*)su,
                                  (const float4*)sd, (float4*)out);
    topk_kernel   <<<8, 256>>>();
    scan_kernel   <<<1, 64>>>();
    scatter_kernel<<<64, 256>>>();
    stage1_kernel <<<dim3(16, 66, 8),  128, S1_SMEM>>>();
    stage2_kernel <<<dim3(16, 66, 16), 128, S2_SMEM>>>(out);
}

// round 17
// speedup vs baseline: 1.0692x; 1.0692x over previous
#include <cuda_runtime.h>
#include <cuda_fp16.h>
#include <cstdint>

#define T_TOK   2048
#define HID     2048
#define NEXP    64
#define INTER   512
#define SINTER  1024
#define TOPK    8
#define ROWS_SHARED 4096
#define ROWS_MOE    (T_TOK*TOPK)
#define ROWS_TOTAL  (ROWS_SHARED + ROWS_MOE)

#define SAH  40    // A smem row stride (halves): K=32 + pad 8
#define SB1  72    // stage1 B f16 row stride (halves): N=64 + pad 8
#define SB2  136   // stage2 B f16 row stride (halves): N=128 + pad 8

// stage sizes (bytes)
#define S1A    (128*SAH*2)    // 10240
#define S1B32  (32*64*4)      // 8192 per matrix
#define S1B16  (32*SB1*2)     // 4608 per matrix per buf
#define S2A    (128*SAH*2)    // 10240
#define S2B32  (32*128*4)     // 16384
#define S2B16  (32*SB2*2)     // 8704

#define NX4   ((long)T_TOK*HID/4)
#define NOUT4 ((long)T_TOK*HID/4)

// ---------------- device scratch ----------------
__device__ float    g_logits[T_TOK*NEXP];
__device__ int      g_sel  [T_TOK*TOPK];
__device__ float    g_selw [T_TOK*TOPK];
__device__ int      g_cnt  [NEXP];
__device__ int      g_off  [NEXP];
__device__ int      g_cur  [NEXP];
__device__ int      g_tok  [ROWS_MOE];
__device__ float    g_tw   [ROWS_MOE];
__device__ __half   g_Hh[(size_t)ROWS_TOTAL*INTER];
__device__ __half   g_x16[(size_t)T_TOK*HID];

// ---------------- helpers ----------------
__device__ __forceinline__ uint32_t smem_u32(const void* p) {
    uint32_t a;
    asm("{ .reg .u64 t; cvta.to.shared.u64 t, %1; cvt.u32.u64 %0, t; }" : "=r"(a) : "l"(p));
    return a;
}
__device__ __forceinline__ uint32_t packh2(float x, float y) {
    __half2 h = __floats2half2_rn(x, y);
    return *(uint32_t*)&h;
}
__device__ __forceinline__ void mma16(float c[4], const uint32_t a[4],
                                      uint32_t b0, uint32_t b1) {
    asm volatile(
        "mma.sync.aligned.m16n8k16.row.col.f32.f16.f16.f32 "
        "{%0,%1,%2,%3}, {%4,%5,%6,%7}, {%8,%9}, {%0,%1,%2,%3};\n"
        : "+f"(c[0]), "+f"(c[1]), "+f"(c[2]), "+f"(c[3])
        : "r"(a[0]), "r"(a[1]), "r"(a[2]), "r"(a[3]), "r"(b0), "r"(b1));
}
__device__ __forceinline__ void ldsm_x4(uint32_t r[4], uint32_t addr) {
    asm volatile("ldmatrix.sync.aligned.m8n8.x4.shared.b16 {%0,%1,%2,%3}, [%4];"
        : "=r"(r[0]), "=r"(r[1]), "=r"(r[2]), "=r"(r[3]) : "r"(addr));
}
__device__ __forceinline__ void ldsm_x4t(uint32_t r[4], uint32_t addr) {
    asm volatile("ldmatrix.sync.aligned.m8n8.x4.trans.shared.b16 {%0,%1,%2,%3}, [%4];"
        : "=r"(r[0]), "=r"(r[1]), "=r"(r[2]), "=r"(r[3]) : "r"(addr));
}
__device__ __forceinline__ void red_add_v2(float* p, float a, float b) {
    asm volatile("red.global.add.v2.f32 [%0], {%1, %2};"
        :: "l"(p), "f"(a), "f"(b) : "memory");
}
__device__ __forceinline__ void cp16(uint32_t dst, const void* src) {
    asm volatile("cp.async.cg.shared.global [%0], [%1], 16;"
        :: "r"(dst), "l"(src) : "memory");
}
#define CP_COMMIT() asm volatile("cp.async.commit_group;" ::: "memory")
#define CP_WAIT1()  asm volatile("cp.async.wait_group 1;"  ::: "memory")
#define CP_WAIT2()  asm volatile("cp.async.wait_group 2;"  ::: "memory")

__device__ __forceinline__ uint2 cvt4(const float4 v) {
    return make_uint2(packh2(v.x, v.y), packh2(v.z, v.w));
}

// ---------------- 0) x conversion + zero out ----------------
__global__ void cvt_x(const float4* __restrict__ x, float4* __restrict__ out) {
    const long i0 = (long)blockIdx.x*blockDim.x + threadIdx.x;
    const long st = (long)gridDim.x*blockDim.x;
    uint2* xd = (uint2*)g_x16;
    for (long i = i0; i < NX4;  i += st) xd[i] = cvt4(x[i]);
    for (long i = i0; i < NOUT4; i += st) out[i] = make_float4(0.f,0.f,0.f,0.f);
}

// ---------------- 1) router GEMM + cnt zero ----------------
__global__ void router_gemm(const float* __restrict__ x, const float* __restrict__ rw) {
    if (blockIdx.x == 0 && threadIdx.x < NEXP) g_cnt[threadIdx.x] = 0;
    __shared__ float As[32][33];
    __shared__ float Bs[32][65];
    const int tid = threadIdx.x;
    const int t0  = blockIdx.x * 32;
    const int m   = tid >> 3, nb = tid & 7;
    float acc[8] = {};
    for (int kt = 0; kt < HID; kt += 32) {
        __syncthreads();
        {   int r = tid >> 3, c = (tid & 7) * 4;
            const float4 v = *(const float4*)(x + (size_t)(t0 + r)*HID + kt + c);
            As[r][c] = v.x; As[r][c+1] = v.y; As[r][c+2] = v.z; As[r][c+3] = v.w; }
        #pragma unroll
        for (int i = 0; i < 8; i++) {
            int idx = tid + i*256; int e = idx >> 5, k = idx & 31;
            Bs[k][e] = rw[(size_t)e*HID + kt + k];
        }
        __syncthreads();
        #pragma unroll
        for (int k = 0; k < 32; k++) {
            float a = As[m][k];
            #pragma unroll
            for (int j = 0; j < 8; j++) acc[j] += a * Bs[k][nb + 8*j];
        }
    }
    #pragma unroll
    for (int j = 0; j < 8; j++) g_logits[(size_t)(t0+m)*NEXP + nb + 8*j] = acc[j];
}

// ---------------- 2) top-k ----------------
__global__ void topk_kernel() {
    int t = blockIdx.x * blockDim.x + threadIdx.x;
    if (t >= T_TOK) return;
    float l[NEXP];
    #pragma unroll
    for (int e = 0; e < NEXP; e++) l[e] = g_logits[(size_t)t*NEXP + e];
    float bw[TOPK]; int bi[TOPK];
    for (int i = 0; i < TOPK; i++) {
        float mv = -1e30f; int mi = 0;
        for (int e = 0; e < NEXP; e++) if (l[e] > mv) { mv = l[e]; mi = e; }
        bw[i] = mv; bi[i] = mi; l[mi] = -1e30f;
    }
    float s = 0.f, mx = bw[0], w[TOPK];
    #pragma unroll
    for (int i = 0; i < TOPK; i++) { w[i] = expf(bw[i] - mx); s += w[i]; }
    float inv = 1.f / s;
    #pragma unroll
    for (int i = 0; i < TOPK; i++) {
        g_sel [t*TOPK+i] = bi[i];
        g_selw[t*TOPK+i] = w[i]*inv;
        atomicAdd(&g_cnt[bi[i]], 1);
    }
}

// ---------------- 3) prefix scan + scatter ----------------
__global__ void scan_kernel() {
    const int i = threadIdx.x;
    __shared__ int tmp[NEXP];
    int v = g_cnt[i];
    tmp[i] = v;
    __syncthreads();
    #pragma unroll
    for (int d = 1; d < NEXP; d <<= 1) {
        int o = (i >= d) ? tmp[i-d] : 0;
        __syncthreads();
        tmp[i] += o;
        __syncthreads();
    }
    int excl = tmp[i] - v;
    g_off[i] = excl; g_cur[i] = excl;
}
__global__ void scatter_kernel() {
    int idx = blockIdx.x*blockDim.x + threadIdx.x;
    if (idx >= T_TOK*TOPK) return;
    int t = idx >> 3;
    int e = g_sel[idx];
    int pos = atomicAdd(&g_cur[e], 1);
    g_tok[pos] = t; g_tw[pos] = g_selw[idx];
}

// ---------------- 4) stage 1: fp32 weights direct, smem convert ------------
// grid (16, 66, 8); CTA M=128, N=64g+64u, K-tile=32, 128 threads
// A ring 4-deep (race fix), B fp32 ring 3-deep, fp16 B ping-pong
#define S1_A    1024
#define S1_BG32 (S1_A    + 4*S1A)
#define S1_BU32 (S1_BG32 + 3*S1B32)
#define S1_BG16 (S1_BU32 + 3*S1B32)
#define S1_BU16 (S1_BG16 + 2*S1B16)
#define S1_SMEM (S1_BU16 + 2*S1B16)
__global__ void __launch_bounds__(128, 2)
stage1_kernel(const float* __restrict__ wg_, const float* __restrict__ wu_,
              const float* __restrict__ sg_, const float* __restrict__ su_) {
    const int s = blockIdx.y;
    int nrows, hbase, ldb, offmoe = 0;
    const float *Bg, *Bu;
    if (s < 2) {
        nrows = T_TOK; hbase = s*T_TOK; ldb = SINTER;
        Bg = sg_ + s*INTER; Bu = su_ + s*INTER;
    } else {
        int e = s - 2;
        nrows = g_cnt[e]; offmoe = g_off[e]; hbase = ROWS_SHARED + offmoe; ldb = INTER;
        Bg = wg_ + (size_t)e*HID*INTER; Bu = wu_ + (size_t)e*HID*INTER;
    }
    const int m0 = blockIdx.x * 128;
    if (m0 >= nrows) return;
    const int n0   = blockIdx.z * 64;
    const int nloc = nrows - m0;

    extern __shared__ char smraw[];
    int*    s_tok = (int*)smraw;
    float*  s_w   = (float*)(smraw + 512);
    const uint32_t aB   = smem_u32(smraw + S1_A);
    float* bg32 = (float*)(smraw + S1_BG32);
    float* bu32 = (float*)(smraw + S1_BU32);
    __half* bg16 = (__half*)(smraw + S1_BG16);
    __half* bu16 = (__half*)(smraw + S1_BU16);
    const uint32_t bg32B = smem_u32(bg32);
    const uint32_t bu32B = smem_u32(bu32);

    const int tid = threadIdx.x;
    {
        int r = m0 + tid;
        if (r < nrows) {
            if (s < 2) { s_tok[tid] = r; s_w[tid] = 1.f; }
            else       { s_tok[tid] = g_tok[offmoe + r]; s_w[tid] = g_tw[offmoe + r]; }
        } else { s_tok[tid] = (s < 2) ? 0 : g_tok[offmoe]; s_w[tid] = 0.f; }
    }
    __syncthreads();

    const int lane = tid & 31, warp = tid >> 5;
    const int wm = warp >> 1, wn = warp & 1;   // 2x2 warps, 64m x (32g+32u)
    const int l4 = lane >> 2, lq = lane & 3;
    const int lr = lane & 15, lc = lane >> 4;
    float cg[4][4][4] = {}, cu[4][4][4] = {};

    const uint32_t aFrag = aB + (uint32_t)(wm*64 + lr)*(SAH*2) + lc*16;
    const uint32_t gFrag = smem_u32(bg16) + (uint32_t)lr*(SB1*2) + wn*64 + lc*16;
    const uint32_t uFrag = smem_u32(bu16) + (uint32_t)lr*(SB1*2) + wn*64 + lc*16;

    // A cp.async: 4 chunks: rows (tid>>2)+32i, col halves (tid&3)*8
    const int arow = tid >> 2, acol = (tid & 3)*8;
    const __half* srcA[4];
    uint32_t dA[4];
    #pragma unroll
    for (int i = 0; i < 4; i++) {
        srcA[i] = g_x16 + (size_t)s_tok[arow + 32*i]*HID + acol;
        dA[i]   = aB + (uint32_t)((arow + 32*i)*SAH + acol)*2;
    }
    // B fp32 cp.async: 4 chunks each: rows (tid>>4)+8i, col floats (tid&15)*4
    const int brow = tid >> 4, bcolf = (tid & 15)*4;
    const float* srcG[4]; const float* srcU[4];
    uint32_t dG[4], dU[4];
    #pragma unroll
    for (int i = 0; i < 4; i++) {
        int r = brow + 8*i;
        srcG[i] = Bg + (size_t)r*ldb + n0 + bcolf;
        srcU[i] = Bu + (size_t)r*ldb + n0 + bcolf;
        dG[i] = bg32B + (uint32_t)(r*64 + bcolf)*4;
        dU[i] = bu32B + (uint32_t)(r*64 + bcolf)*4;
    }

    const int NT = HID / 32;
    auto issue = [&](int tile) {
        int stA = tile & 3, stB = tile % 3, kt = tile * 32;
        #pragma unroll
        for (int i = 0; i < 4; i++) cp16(dA[i] + stA*S1A, srcA[i] + kt);
        #pragma unroll
        for (int i = 0; i < 4; i++) {
            cp16(dG[i] + stB*S1B32, srcG[i] + (size_t)kt*ldb);
            cp16(dU[i] + stB*S1B32, srcU[i] + (size_t)kt*ldb);
        }
    };
    const int crow = tid >> 3, ccolf = (tid & 7)*8;
    auto cvt = [&](int tile, int buf) {
        int st = tile % 3;
        const float* g32 = bg32 + st*(S1B32/4);
        const float* u32 = bu32 + st*(S1B32/4);
        __half* g16 = bg16 + buf*(S1B16/2);
        __half* u16 = bu16 + buf*(S1B16/2);
        #pragma unroll
        for (int i = 0; i < 2; i++) {
            int r = crow + 16*i;
            float4 a0 = *(const float4*)(g32 + r*64 + ccolf);
            float4 a1 = *(const float4*)(g32 + r*64 + ccolf + 4);
            uint2 p0 = cvt4(a0), p1 = cvt4(a1);
            *(uint4*)(g16 + r*SB1 + ccolf) = make_uint4(p0.x, p0.y, p1.x, p1.y);
            float4 b0 = *(const float4*)(u32 + r*64 + ccolf);
            float4 b1 = *(const float4*)(u32 + r*64 + ccolf + 4);
            uint2 q0 = cvt4(b0), q1 = cvt4(b1);
            *(uint4*)(u16 + r*SB1 + ccolf) = make_uint4(q0.x, q0.y, q1.x, q1.y);
        }
    };
    auto comp = [&](int tile, int buf) {
        const uint32_t aOff = aFrag + (uint32_t)(tile & 3)*S1A;
        const uint32_t gOff = gFrag + (uint32_t)buf*S1B16;
        const uint32_t uOff = uFrag + (uint32_t)buf*S1B16;
        #pragma unroll
        for (int ks = 0; ks < 2; ks++) {
            uint32_t a[4][4], bg[2][4], bu[2][4];
            #pragma unroll
            for (int mi = 0; mi < 4; mi++)
                ldsm_x4(a[mi], aOff + mi*16*(SAH*2) + ks*32);
            #pragma unroll
            for (int ni = 0; ni < 2; ni++) {
                ldsm_x4t(bg[ni], gOff + ks*16*(SB1*2) + ni*32);
                ldsm_x4t(bu[ni], uOff + ks*16*(SB1*2) + ni*32);
            }
            #pragma unroll
            for (int mi = 0; mi < 4; mi++)
                #pragma unroll
                for (int ni = 0; ni < 2; ni++) {
                    mma16(cg[mi][2*ni],   a[mi], bg[ni][0], bg[ni][1]);
                    mma16(cg[mi][2*ni+1], a[mi], bg[ni][2], bg[ni][3]);
                    mma16(cu[mi][2*ni],   a[mi], bu[ni][0], bu[ni][1]);
                    mma16(cu[mi][2*ni+1], a[mi], bu[ni][2], bu[ni][3]);
                }
        }
    };

    issue(0); CP_COMMIT();
    issue(1); CP_COMMIT();
    issue(2); CP_COMMIT();
    CP_WAIT2();
    __syncthreads();
    cvt(0, 0);
    #pragma unroll 1
    for (int it = 0; it < NT; it++) {
        CP_WAIT1();
        __syncthreads();
        if (it + 1 < NT) cvt(it + 1, (it + 1) & 1);
        if (it + 3 < NT) issue(it + 3);
        CP_COMMIT();
        comp(it, it & 1);
    }

    // epilogue: silu(gate)*up*weight -> fp16 H
    #pragma unroll
    for (int mi = 0; mi < 4; mi++) {
        int r0 = wm*64 + mi*16 + l4;
        int r1 = r0 + 8;
        float w0 = (r0 < nloc) ? s_w[r0] : 0.f;
        float w1 = (r1 < nloc) ? s_w[r1] : 0.f;
        #pragma unroll
        for (int nj = 0; nj < 4; nj++) {
            int c = wn*32 + nj*8 + 2*lq;
            if (r0 < nloc) {
                float g0 = cg[mi][nj][0], u0 = cu[mi][nj][0];
                float g1 = cg[mi][nj][1], u1 = cu[mi][nj][1];
                float h0 = g0 / (1.f + __expf(-g0)) * u0 * w0;
                float h1 = g1 / (1.f + __expf(-g1)) * u1 * w0;
                *(uint32_t*)(g_Hh + (size_t)(hbase + m0 + r0)*INTER + n0 + c) = packh2(h0, h1);
            }
            if (r1 < nloc) {
                float g2 = cg[mi][nj][2], u2 = cu[mi][nj][2];
                float g3 = cg[mi][nj][3], u3 = cu[mi][nj][3];
                float h2 = g2 / (1.f + __expf(-g2)) * u2 * w1;
                float h3 = g3 / (1.f + __expf(-g3)) * u3 * w1;
                *(uint32_t*)(g_Hh + (size_t)(hbase + m0 + r1)*INTER + n0 + c) = packh2(h2, h3);
            }
        }
    }
}

// ---------------- 5) stage 2: fp32 weights direct, smem convert ------------
// grid (16, 66, 16); CTA M=128, N=128, K-tile=32, 128 threads
#define S2_A    512
#define S2_B32  (S2_A   + 4*S2A)
#define S2_B16  (S2_B32 + 3*S2B32)
#define S2_SMEM (S2_B16 + 2*S2B16)
__global__ void __launch_bounds__(128, 2)
stage2_kernel(const float* __restrict__ wd_, const float* __restrict__ sd_,
              float* __restrict__ out) {
    const int s = blockIdx.y;
    int nrows, hbase, offmoe = 0; const float* Bd;
    if (s < 2) { nrows = T_TOK; hbase = s*T_TOK; Bd = sd_ + (size_t)s*INTER*HID; }
    else { int e = s-2; nrows = g_cnt[e]; offmoe = g_off[e]; hbase = ROWS_SHARED + offmoe;
           Bd = wd_ + (size_t)e*INTER*HID; }
    const int m0 = blockIdx.x * 128;
    if (m0 >= nrows) return;
    const int n0   = blockIdx.z * 128;
    const int nloc = nrows - m0;

    extern __shared__ char smraw[];
    int* s_tok = (int*)smraw;
    const uint32_t aB = smem_u32(smraw + S2_A);
    float* b32 = (float*)(smraw + S2_B32);
    __half* b16 = (__half*)(smraw + S2_B16);
    const uint32_t b32B = smem_u32(b32);

    const int tid = threadIdx.x, lane = tid & 31, warp = tid >> 5;
    {
        int r = m0 + tid;
        if (r < nrows) s_tok[tid] = (s < 2) ? r : g_tok[offmoe + r];
        else           s_tok[tid] = 0;
    }
    __syncthreads();

    const int wm = warp >> 1, wn = warp & 1;   // 2x2 warps, 64x64 tile
    const int l4 = lane >> 2, lq = lane & 3;
    const int lr = lane & 15, lc = lane >> 4;
    float cc[4][8][4] = {};

    const uint32_t aFrag = aB + (uint32_t)(wm*64 + lr)*(SAH*2) + lc*16;
    const uint32_t bFrag = smem_u32(b16) + (uint32_t)lr*(SB2*2) + wn*128 + lc*16;

    const int arow = tid >> 2, acol = (tid & 3)*8;
    const __half* srcA[4];
    uint32_t dA[4];
    #pragma unroll
    for (int i = 0; i < 4; i++) {
        int r = arow + 32*i;
        int rr = (r < nloc) ? r : 0;
        srcA[i] = g_Hh + (size_t)(hbase + m0 + rr)*INTER + acol;
        dA[i]   = aB + (uint32_t)(r*SAH + acol)*2;
    }
    const int brow = tid >> 5, bcolf = (tid & 31)*4;
    const float* srcB[8];
    uint32_t dB[8];
    #pragma unroll
    for (int i = 0; i < 8; i++) {
        int r = brow + 4*i;
        srcB[i] = Bd + (size_t)r*HID + n0 + bcolf;
        dB[i]   = b32B + (uint32_t)(r*128 + bcolf)*4;
    }

    const int NT = INTER / 32;
    auto issue = [&](int tile) {
        int stA = tile & 3, stB = tile % 3, kt = tile * 32;
        #pragma unroll
        for (int i = 0; i < 4; i++) cp16(dA[i] + stA*S2A, srcA[i] + kt);
        #pragma unroll
        for (int i = 0; i < 8; i++) cp16(dB[i] + stB*S2B32, srcB[i] + (size_t)kt*HID);
    };
    const int crow = tid >> 4, ccolf = (tid & 15)*8;
    auto cvt = [&](int tile, int buf) {
        int st = tile % 3;
        const float* s32 = b32 + st*(S2B32/4);
        __half* s16 = b16 + buf*(S2B16/2);
        #pragma unroll
        for (int i = 0; i < 4; i++) {
            int r = crow + 8*i;
            float4 a0 = *(const float4*)(s32 + r*128 + ccolf);
            float4 a1 = *(const float4*)(s32 + r*128 + ccolf + 4);
            uint2 p0 = cvt4(a0), p1 = cvt4(a1);
            *(uint4*)(s16 + r*SB2 + ccolf) = make_uint4(p0.x, p0.y, p1.x, p1.y);
        }
    };
    auto comp = [&](int tile, int buf) {
        const uint32_t aOff = aFrag + (uint32_t)(tile & 3)*S2A;
        const uint32_t bOff = bFrag + (uint32_t)buf*S2B16;
        #pragma unroll
        for (int ks = 0; ks < 2; ks++) {
            uint32_t a[4][4], b[4][4];
            #pragma unroll
            for (int mi = 0; mi < 4; mi++)
                ldsm_x4(a[mi], aOff + mi*16*(SAH*2) + ks*32);
            #pragma unroll
            for (int ni = 0; ni < 4; ni++)
                ldsm_x4t(b[ni], bOff + ks*16*(SB2*2) + ni*32);
            #pragma unroll
            for (int mi = 0; mi < 4; mi++)
                #pragma unroll
                for (int ni = 0; ni < 4; ni++) {
                    mma16(cc[mi][2*ni],   a[mi], b[ni][0], b[ni][1]);
                    mma16(cc[mi][2*ni+1], a[mi], b[ni][2], b[ni][3]);
                }
        }
    };

    issue(0); CP_COMMIT();
    issue(1); CP_COMMIT();
    issue(2); CP_COMMIT();
    CP_WAIT2();
    __syncthreads();
    cvt(0, 0);
    #pragma unroll 1
    for (int it = 0; it < NT; it++) {
        CP_WAIT1();
        __syncthreads();
        if (it + 1 < NT) cvt(it + 1, (it + 1) & 1);
        if (it + 3 < NT) issue(it + 3);
        CP_COMMIT();
        comp(it, it & 1);
    }

    // fused combine: reduce into out[token, n]
    #pragma unroll
    for (int mi = 0; mi < 4; mi++) {
        int r0 = wm*64 + mi*16 + l4;
        int r1 = r0 + 8;
        int tk0 = s_tok[r0], tk1 = s_tok[r1];
        #pragma unroll
        for (int nj = 0; nj < 8; nj++) {
            int c = n0 + wn*64 + nj*8 + 2*lq;
            if (r0 < nloc)
                red_add_v2(out + (size_t)tk0*HID + c, cc[mi][nj][0], cc[mi][nj][1]);
            if (r1 < nloc)
                red_add_v2(out + (size_t)tk1*HID + c, cc[mi][nj][2], cc[mi][nj][3]);
        }
    }
}

// ---------------- launch (serial stream) ----------------
extern "C" void kernel_launch(void* const* d_in, const int* in_sizes, int n_in,
                              void* d_out, int out_size) {
    const float* x  = (const float*)d_in[0];
    const float* rw = (const float*)d_in[1];
    const float* wg = (const float*)d_in[2];
    const float* wu = (const float*)d_in[3];
    const float* wd = (const float*)d_in[4];
    const float* sg = (const float*)d_in[5];
    const float* su = (const float*)d_in[6];
    const float* sd = (const float*)d_in[7];
    float* out = (float*)d_out;

    static bool attr_done = false;
    if (!attr_done) {
        cudaFuncSetAttribute(stage1_kernel, cudaFuncAttributeMaxDynamicSharedMemorySize, S1_SMEM);
        cudaFuncSetAttribute(stage2_kernel, cudaFuncAttributeMaxDynamicSharedMemorySize, S2_SMEM);
        attr_done = true;
    }

    router_gemm   <<<64, 256>>>(x, rw);
    cvt_x         <<<1024, 256>>>((const float4*)x, (float4*)out);
    topk_kernel   <<<8, 256>>>();
    scan_kernel   <<<1, 64>>>();
    scatter_kernel<<<64, 256>>>();
    stage1_kernel <<<dim3(16, 66, 8),  128, S1_SMEM>>>(wg, wu, sg, su);
    stage2_kernel <<<dim3(16, 66, 16), 128, S2_SMEM>>>(wd, sd, out);
}